// round 1
// baseline (speedup 1.0000x reference)
#include <cuda_runtime.h>
#include <cuda_bf16.h>
#include <cstdint>

// Sinkhorn, 32 x 1024 x 1024, tau=1, 10 iterations.
// Linear-domain rank-1 scaling formulation:
//   E = exp(s); a = b = 1
//   even iter: a_i = 1 / sum_j E_ij * b_j
//   odd  iter: b_j = 1 / sum_i E_ij * a_i
//   out_ij = exp(s_ij) * a_i * b_j
// E stored once in bf16 (64MB scratch) for the 9 GEMV passes;
// the final pass recomputes exp(s) in fp32 for full output accuracy.

#define BATCH 32
#define N 1024
#define RCH 16                      // row chunks for the column (E^T a) pass
#define RPC (N / RCH)               // rows per chunk = 64

__device__ __nv_bfloat16 g_E[(size_t)BATCH * N * N];   // 64 MB scratch
__device__ float g_part[RCH][BATCH][N];                // 2 MB partials
__device__ float g_a[BATCH * N];
__device__ float g_b[BATCH * N];

// ---------------------------------------------------------------------------
__device__ __forceinline__ float block_reduce_sum_256(float v) {
    __shared__ float sh[8];
    const int lane = threadIdx.x & 31;
    const int wid  = threadIdx.x >> 5;
    #pragma unroll
    for (int o = 16; o > 0; o >>= 1) v += __shfl_down_sync(0xFFFFFFFFu, v, o);
    if (lane == 0) sh[wid] = v;
    __syncthreads();
    if (wid == 0) {
        v = (lane < 8) ? sh[lane] : 0.0f;
        #pragma unroll
        for (int o = 4; o > 0; o >>= 1) v += __shfl_down_sync(0xFFFFFFFFu, v, o);
    }
    return v;  // valid on thread 0
}

// ---------------------------------------------------------------------------
// K1: E = exp(s) -> bf16; row sums of exact fp32 exp; a_i = 1/rowsum
// grid (N, BATCH), 256 threads, 4 floats per thread
__global__ void k_exp_rowsum(const float* __restrict__ s) {
    const int row = blockIdx.x;
    const int b   = blockIdx.y;
    const size_t base = ((size_t)b * N + row) * N;
    const int j0 = threadIdx.x * 4;

    float4 sv = *reinterpret_cast<const float4*>(s + base + j0);
    float e0 = __expf(sv.x), e1 = __expf(sv.y);
    float e2 = __expf(sv.z), e3 = __expf(sv.w);

    // pack 4 bf16 into 8 bytes
    __nv_bfloat162 p0 = __floats2bfloat162_rn(e0, e1);
    __nv_bfloat162 p1 = __floats2bfloat162_rn(e2, e3);
    uint2 packed;
    packed.x = *reinterpret_cast<uint32_t*>(&p0);
    packed.y = *reinterpret_cast<uint32_t*>(&p1);
    *reinterpret_cast<uint2*>(&g_E[base + j0]) = packed;

    float v = block_reduce_sum_256(e0 + e1 + e2 + e3);
    if (threadIdx.x == 0) g_a[b * N + row] = 1.0f / v;
}

// ---------------------------------------------------------------------------
// Column pass stage 1: partial sums over a row-chunk of E^T * a
// grid (RCH, BATCH), 256 threads; thread t owns columns 4t..4t+3
__global__ void k_col_partial() {
    const int chunk = blockIdx.x;
    const int b     = blockIdx.y;
    const int j0    = threadIdx.x * 4;
    const int i0    = chunk * RPC;

    __shared__ float sa[RPC];
    if (threadIdx.x < RPC) sa[threadIdx.x] = g_a[b * N + i0 + threadIdx.x];
    __syncthreads();

    float acc0 = 0.f, acc1 = 0.f, acc2 = 0.f, acc3 = 0.f;
    #pragma unroll 4
    for (int r = 0; r < RPC; ++r) {
        const size_t off = ((size_t)b * N + (i0 + r)) * N + j0;
        uint2 u = *reinterpret_cast<const uint2*>(&g_E[off]);
        __nv_bfloat162 p0 = *reinterpret_cast<__nv_bfloat162*>(&u.x);
        __nv_bfloat162 p1 = *reinterpret_cast<__nv_bfloat162*>(&u.y);
        float2 f0 = __bfloat1622float2(p0);
        float2 f1 = __bfloat1622float2(p1);
        const float av = sa[r];
        acc0 = fmaf(av, f0.x, acc0);
        acc1 = fmaf(av, f0.y, acc1);
        acc2 = fmaf(av, f1.x, acc2);
        acc3 = fmaf(av, f1.y, acc3);
    }
    float4 out = make_float4(acc0, acc1, acc2, acc3);
    *reinterpret_cast<float4*>(&g_part[chunk][b][j0]) = out;
}

// Column pass stage 2: b_j = 1 / sum_chunks partial
// grid (BATCH*N/256), 256 threads
__global__ void k_col_combine() {
    const int idx = blockIdx.x * blockDim.x + threadIdx.x;  // b*N + j
    const int b = idx >> 10;
    const int j = idx & (N - 1);
    float s = 0.f;
    #pragma unroll
    for (int c = 0; c < RCH; ++c) s += g_part[c][b][j];
    g_b[idx] = 1.0f / s;
}

// ---------------------------------------------------------------------------
// Row pass: a_i = 1 / sum_j E_ij * b_j
// grid (N, BATCH), 256 threads, 4 elems per thread
__global__ void k_row() {
    const int row = blockIdx.x;
    const int b   = blockIdx.y;
    const size_t base = ((size_t)b * N + row) * N;
    const int j0 = threadIdx.x * 4;

    uint2 u = *reinterpret_cast<const uint2*>(&g_E[base + j0]);
    __nv_bfloat162 p0 = *reinterpret_cast<__nv_bfloat162*>(&u.x);
    __nv_bfloat162 p1 = *reinterpret_cast<__nv_bfloat162*>(&u.y);
    float2 f0 = __bfloat1622float2(p0);
    float2 f1 = __bfloat1622float2(p1);
    float4 bv = *reinterpret_cast<const float4*>(&g_b[b * N + j0]);

    float v = f0.x * bv.x + f0.y * bv.y + f1.x * bv.z + f1.y * bv.w;
    v = block_reduce_sum_256(v);
    if (threadIdx.x == 0) g_a[b * N + row] = 1.0f / v;
}

// ---------------------------------------------------------------------------
// Final: out_ij = exp(s_ij) * a_i * b_j   (fp32 exp recomputed from s)
// grid (N, BATCH), 256 threads, 4 elems per thread
__global__ void k_final(const float* __restrict__ s, float* __restrict__ out) {
    const int row = blockIdx.x;
    const int b   = blockIdx.y;
    const size_t base = ((size_t)b * N + row) * N;
    const int j0 = threadIdx.x * 4;

    const float a = g_a[b * N + row];
    float4 bv = *reinterpret_cast<const float4*>(&g_b[b * N + j0]);
    float4 sv = *reinterpret_cast<const float4*>(s + base + j0);

    float4 o;
    o.x = __expf(sv.x) * (a * bv.x);
    o.y = __expf(sv.y) * (a * bv.y);
    o.z = __expf(sv.z) * (a * bv.z);
    o.w = __expf(sv.w) * (a * bv.w);
    *reinterpret_cast<float4*>(out + base + j0) = o;
}

// ---------------------------------------------------------------------------
extern "C" void kernel_launch(void* const* d_in, const int* in_sizes, int n_in,
                              void* d_out, int out_size) {
    const float* s = (const float*)d_in[0];
    float* out = (float*)d_out;

    dim3 rows_grid(N, BATCH);

    // iter 0 (row normalize) fused with exp+pack
    k_exp_rowsum<<<rows_grid, 256>>>(s);

    // iters 1..9: odd = column update (b), even = row update (a)
    for (int it = 1; it <= 9; ++it) {
        if (it & 1) {
            k_col_partial<<<dim3(RCH, BATCH), 256>>>();
            k_col_combine<<<(BATCH * N) / 256, 256>>>();
        } else {
            k_row<<<rows_grid, 256>>>();
        }
    }

    k_final<<<rows_grid, 256>>>(s, out);
}

// round 2
// speedup vs baseline: 1.3770x; 1.3770x over previous
#include <cuda_runtime.h>
#include <cuda_bf16.h>
#include <cstdint>

// Sinkhorn, 32 x 1024 x 1024, tau=1, 10 iterations.
// Linear-domain rank-1 scaling:
//   E = exp(s); even iter: a_i = 1/sum_j E_ij b_j ; odd iter: b_j = 1/sum_i E_ij a_i
//   out = exp(s) * a_i * b_j
// E cached once in bf16 (64 MB, L2-resident-ish); final pass recomputes exp in fp32.

#define BATCH 32
#define N 1024

__device__ __nv_bfloat16 g_E[(size_t)BATCH * N * N];   // 64 MB scratch
__device__ float g_a[BATCH * N];
__device__ float g_b[BATCH * N];

// ---------------------------------------------------------------------------
// K1: E = exp(s) -> bf16; a_i = 1/rowsum. Warp per row, 8 rows per block.
// grid (N/8, BATCH), 256 threads. Lane handles 32 floats (8x float4, MLP=8).
__global__ void k_exp_rowsum(const float* __restrict__ s) {
    const int w    = threadIdx.x >> 5;
    const int lane = threadIdx.x & 31;
    const int row  = blockIdx.x * 8 + w;
    const int b    = blockIdx.y;
    const size_t base = ((size_t)b * N + row) * N;

    float sum = 0.f;
    #pragma unroll
    for (int k = 0; k < 8; ++k) {
        const int j = (lane + 32 * k) * 4;
        float4 sv = *reinterpret_cast<const float4*>(s + base + j);
        float e0 = __expf(sv.x), e1 = __expf(sv.y);
        float e2 = __expf(sv.z), e3 = __expf(sv.w);
        __nv_bfloat162 p0 = __floats2bfloat162_rn(e0, e1);
        __nv_bfloat162 p1 = __floats2bfloat162_rn(e2, e3);
        uint2 packed;
        packed.x = *reinterpret_cast<uint32_t*>(&p0);
        packed.y = *reinterpret_cast<uint32_t*>(&p1);
        *reinterpret_cast<uint2*>(&g_E[base + j]) = packed;
        sum += (e0 + e1) + (e2 + e3);
    }
    #pragma unroll
    for (int o = 16; o > 0; o >>= 1) sum += __shfl_down_sync(0xFFFFFFFFu, sum, o);
    if (lane == 0) g_a[b * N + row] = 1.0f / sum;
}

// ---------------------------------------------------------------------------
// Row pass: a_i = 1/sum_j E_ij b_j. Warp per row, 8 rows per block.
// grid (N/8, BATCH), 256 threads. Lane: 8x (uint2 E load + float4 b load).
__global__ void k_row() {
    const int w    = threadIdx.x >> 5;
    const int lane = threadIdx.x & 31;
    const int row  = blockIdx.x * 8 + w;
    const int b    = blockIdx.y;
    const size_t base = ((size_t)b * N + row) * N;
    const float4* __restrict__ bp = reinterpret_cast<const float4*>(&g_b[b * N]);

    float sum = 0.f;
    #pragma unroll
    for (int k = 0; k < 8; ++k) {
        const int j = (lane + 32 * k) * 4;
        uint2 u = *reinterpret_cast<const uint2*>(&g_E[base + j]);
        __nv_bfloat162 p0 = *reinterpret_cast<__nv_bfloat162*>(&u.x);
        __nv_bfloat162 p1 = *reinterpret_cast<__nv_bfloat162*>(&u.y);
        float2 f0 = __bfloat1622float2(p0);
        float2 f1 = __bfloat1622float2(p1);
        float4 bv = bp[j >> 2];
        sum += f0.x * bv.x + f0.y * bv.y + f1.x * bv.z + f1.y * bv.w;
    }
    #pragma unroll
    for (int o = 16; o > 0; o >>= 1) sum += __shfl_down_sync(0xFFFFFFFFu, sum, o);
    if (lane == 0) g_a[b * N + row] = 1.0f / sum;
}

// ---------------------------------------------------------------------------
// Column pass: b_j = 1/sum_i E_ij a_i. Block owns 64 columns x all rows.
// grid (N/64, BATCH), 256 threads (8 warps). Warp w reads rows w, w+8, ...;
// lane owns 2 adjacent columns (4B bf16x2 load -> 128B coalesced per warp).
// 4-row unroll for MLP. a staged in shared; cross-warp reduce in shared.
__global__ void k_col() {
    __shared__ float sa[N];
    __shared__ float red[8][64];
    const int b  = blockIdx.y;
    const int j0 = blockIdx.x * 64;
    const int w    = threadIdx.x >> 5;
    const int lane = threadIdx.x & 31;

    // stage a[b, :] into shared (256 threads x 1 float4)
    {
        const float4* ap = reinterpret_cast<const float4*>(&g_a[b * N]);
        reinterpret_cast<float4*>(sa)[threadIdx.x] = ap[threadIdx.x];
    }
    __syncthreads();

    const size_t bbase = (size_t)b * N * N;
    const int col = j0 + lane * 2;

    float acc0 = 0.f, acc1 = 0.f;
    #pragma unroll 1
    for (int it = 0; it < 128; it += 4) {
        float2 f[4];
        float  av[4];
        #pragma unroll
        for (int u = 0; u < 4; ++u) {
            const int r = (it + u) * 8 + w;
            uint32_t uu = *reinterpret_cast<const uint32_t*>(
                &g_E[bbase + (size_t)r * N + col]);
            f[u]  = __bfloat1622float2(*reinterpret_cast<__nv_bfloat162*>(&uu));
            av[u] = sa[r];
        }
        #pragma unroll
        for (int u = 0; u < 4; ++u) {
            acc0 = fmaf(av[u], f[u].x, acc0);
            acc1 = fmaf(av[u], f[u].y, acc1);
        }
    }
    red[w][lane * 2]     = acc0;
    red[w][lane * 2 + 1] = acc1;
    __syncthreads();

    if (threadIdx.x < 64) {
        float s = 0.f;
        #pragma unroll
        for (int ww = 0; ww < 8; ++ww) s += red[ww][threadIdx.x];
        g_b[b * N + j0 + threadIdx.x] = 1.0f / s;
    }
}

// ---------------------------------------------------------------------------
// Final: out = exp(s) * a_i * b_j. Warp per row, 8 rows per block.
__global__ void k_final(const float* __restrict__ s, float* __restrict__ out) {
    const int w    = threadIdx.x >> 5;
    const int lane = threadIdx.x & 31;
    const int row  = blockIdx.x * 8 + w;
    const int b    = blockIdx.y;
    const size_t base = ((size_t)b * N + row) * N;

    const float a = g_a[b * N + row];
    const float4* __restrict__ bp = reinterpret_cast<const float4*>(&g_b[b * N]);

    #pragma unroll
    for (int k = 0; k < 8; ++k) {
        const int j = (lane + 32 * k) * 4;
        float4 sv = *reinterpret_cast<const float4*>(s + base + j);
        float4 bv = bp[j >> 2];
        float4 o;
        o.x = __expf(sv.x) * (a * bv.x);
        o.y = __expf(sv.y) * (a * bv.y);
        o.z = __expf(sv.z) * (a * bv.z);
        o.w = __expf(sv.w) * (a * bv.w);
        *reinterpret_cast<float4*>(out + base + j) = o;
    }
}

// ---------------------------------------------------------------------------
extern "C" void kernel_launch(void* const* d_in, const int* in_sizes, int n_in,
                              void* d_out, int out_size) {
    const float* s = (const float*)d_in[0];
    float* out = (float*)d_out;

    dim3 rows_grid(N / 8, BATCH);   // (128, 32)
    dim3 cols_grid(N / 64, BATCH);  // (16, 32)

    k_exp_rowsum<<<rows_grid, 256>>>(s);           // iter 0 (row) fused

    for (int it = 1; it <= 9; ++it) {
        if (it & 1) k_col<<<cols_grid, 256>>>();   // odd: update b
        else        k_row<<<rows_grid, 256>>>();   // even: update a
    }

    k_final<<<rows_grid, 256>>>(s, out);
}